// round 11
// baseline (speedup 1.0000x reference)
#include <cuda_runtime.h>
#include <cuda_fp16.h>
#include <math.h>
#include <stdint.h>

#define D_FEAT 128
#define HID 64

// Per-node projected features in fp16 (25.6 MB, L2-resident).
__device__ __half g_yh[(size_t)100000 * 128];
// c vector (float) + bias
__device__ float g_c[HID + 1];
// half2-packed c and W2 for the edge kernel
__device__ __half2 g_ch2[HID / 2];
__device__ __half2 g_w2h2[HID / 2];

// ---------------------------------------------------------------------------
// Kernel 1: node GEMM via mma.sync.m16n8k16 (fp16 in, fp32 accum).
// y[M x 128] = embed[M x 128] @ Wc[128 x 128], fp16 output to g_yh.
// CTA: 128x128 tile, 512 threads = 16 warps (4 M x 4 N), warp tile 32x32.
// ~80 regs/thread -> no spills; 16 warps hide phase latency.
// Block nblk computes the edge-invariant c vector instead.
// ---------------------------------------------------------------------------
#define SROW 272            // bytes per padded smem row (136 halves)
#define SM_A 0              // A tile: 128 * 272 = 34816 B
#define SM_B 34816          // B tile: 128 * 272 = 34816 B
#define SM_TOTAL 69632

__device__ __forceinline__ void mma16816(float* c, const uint32_t* a,
                                         const uint32_t* b) {
    asm volatile(
        "mma.sync.aligned.m16n8k16.row.col.f32.f16.f16.f32 "
        "{%0,%1,%2,%3}, {%4,%5,%6,%7}, {%8,%9}, {%0,%1,%2,%3};"
        : "+f"(c[0]), "+f"(c[1]), "+f"(c[2]), "+f"(c[3])
        : "r"(a[0]), "r"(a[1]), "r"(a[2]), "r"(a[3]), "r"(b[0]), "r"(b[1]));
}

__global__ __launch_bounds__(512, 1)
void node_gemm_mma(const float* __restrict__ embed,
                   const float* __restrict__ W1,
                   const float* __restrict__ b1,
                   const float* __restrict__ W2,
                   const float* __restrict__ b2,
                   const int* __restrict__ srcp,
                   const int* __restrict__ dstp,
                   int M, int nblk) {
    extern __shared__ char smem[];
    int tid = threadIdx.x;

    if (blockIdx.x == (unsigned)nblk) {
        // ---- c vector block: c = emb[src]@W1[256:384] + emb[dst]@W1[384:512] + b1
        __shared__ float part[8][HID];
        int j = tid & 63;
        int g = tid >> 6;   // 0..7, each handles 32 t-values
        int s = srcp[0];
        int d = dstp[0];
        const float* es = embed + (size_t)s * D_FEAT;
        const float* ed = embed + (size_t)d * D_FEAT;
        float acc = 0.f;
#pragma unroll 8
        for (int t = g * 32; t < g * 32 + 32; ++t) {
            float e = (t < 128) ? es[t] : ed[t - 128];
            acc = fmaf(e, W1[(256 + t) * HID + j], acc);  // 256+t == 384+(t-128)
        }
        part[g][j] = acc;
        __syncthreads();
        if (tid < 64) {
            float cj = b1[j];
#pragma unroll
            for (int g2 = 0; g2 < 8; ++g2) cj += part[g2][j];
            g_c[j] = cj;
            part[0][j] = cj;
            if (j == 0) g_c[HID] = b2[0];
        }
        __syncthreads();
        if (tid < 32) {
            g_ch2[tid]  = __floats2half2_rn(part[0][2 * tid], part[0][2 * tid + 1]);
            g_w2h2[tid] = __floats2half2_rn(W2[2 * tid], W2[2 * tid + 1]);
        }
        return;
    }

    int row0 = blockIdx.x * 128;
    int rows = M - row0;
    if (rows > 128) rows = 128;

    // Build WcT smem tile from W1 as half2 pairs along k.
    // idx in [0,8192): j = idx & 127 (output col), kh = idx >> 7 (k pair).
    // Wc[k][j] = (j<64) ? W1[k][j] : W1[128+k][j-64]; W1 rows are 64 floats.
    for (int idx = tid; idx < 8192; idx += 512) {
        int j  = idx & 127;
        int kh = idx >> 7;
        int c  = (j < 64) ? j : j - 64;
        int base = (j < 64) ? 0 : 128;
        float v0 = W1[(base + 2 * kh) * HID + c];
        float v1 = W1[(base + 2 * kh + 1) * HID + c];
        *(__half2*)(smem + SM_B + j * SROW + 4 * kh) = __floats2half2_rn(v0, v1);
    }

    // Load + convert A tile: chunk = 8 floats -> 8 halves (16 B)
    for (int idx = tid; idx < 2048; idx += 512) {
        int r  = idx >> 4;
        int cc = idx & 15;
        float4 f0, f1;
        if (r < rows) {
            const float* src = embed + (size_t)(row0 + r) * 128 + cc * 8;
            f0 = *(const float4*)src;
            f1 = *(const float4*)(src + 4);
        } else {
            f0 = f1 = make_float4(0.f, 0.f, 0.f, 0.f);
        }
        __half2 h[4];
        h[0] = __floats2half2_rn(f0.x, f0.y);
        h[1] = __floats2half2_rn(f0.z, f0.w);
        h[2] = __floats2half2_rn(f1.x, f1.y);
        h[3] = __floats2half2_rn(f1.z, f1.w);
        *(uint4*)(smem + SM_A + r * SROW + cc * 16) = *(uint4*)h;
    }
    __syncthreads();

    int w    = tid >> 5;
    int lane = tid & 31;
    int g    = lane >> 2;
    int tg   = lane & 3;
    int mw   = (w & 3) * 32;     // 4 M-blocks
    int nw   = (w >> 2) * 32;    // 4 N-blocks

    float acc[2][4][4];
#pragma unroll
    for (int mi = 0; mi < 2; ++mi)
#pragma unroll
        for (int nj = 0; nj < 4; ++nj)
#pragma unroll
            for (int q = 0; q < 4; ++q) acc[mi][nj][q] = 0.f;

    const char* pa0 = smem + SM_A + (mw + g) * SROW + tg * 4;
    const char* pb0 = smem + SM_B + (nw + g) * SROW + tg * 4;

#pragma unroll
    for (int ks = 0; ks < 8; ++ks) {
        int kb = ks * 32;
        uint32_t a[2][4];
#pragma unroll
        for (int mi = 0; mi < 2; ++mi) {
            const char* p = pa0 + mi * 16 * SROW + kb;
            a[mi][0] = *(const uint32_t*)p;
            a[mi][1] = *(const uint32_t*)(p + 8 * SROW);
            a[mi][2] = *(const uint32_t*)(p + 16);
            a[mi][3] = *(const uint32_t*)(p + 8 * SROW + 16);
        }
        uint32_t b[4][2];
#pragma unroll
        for (int nj = 0; nj < 4; ++nj) {
            const char* p = pb0 + nj * 8 * SROW + kb;
            b[nj][0] = *(const uint32_t*)p;
            b[nj][1] = *(const uint32_t*)(p + 16);
        }
#pragma unroll
        for (int mi = 0; mi < 2; ++mi)
#pragma unroll
            for (int nj = 0; nj < 4; ++nj)
                mma16816(acc[mi][nj], a[mi], b[nj]);
    }

#pragma unroll
    for (int mi = 0; mi < 2; ++mi) {
        int r0 = row0 + mw + mi * 16 + g;
        int r1 = r0 + 8;
#pragma unroll
        for (int nj = 0; nj < 4; ++nj) {
            int jc = nw + nj * 8 + tg * 2;
            if (r0 < M)
                *(__half2*)(g_yh + (size_t)r0 * 128 + jc) =
                    __floats2half2_rn(acc[mi][nj][0], acc[mi][nj][1]);
            if (r1 < M)
                *(__half2*)(g_yh + (size_t)r1 * 128 + jc) =
                    __floats2half2_rn(acc[mi][nj][2], acc[mi][nj][3]);
        }
    }
}

// ---------------------------------------------------------------------------
// Kernel 2: edge kernel — 8 edges per warp iteration (2 quads), 8 lanes/edge,
// half2 math. Gate: sigmoid(logit(n)+s) == n*exp(s) / (n*exp(s) + 1 - n).
// ---------------------------------------------------------------------------
__global__ void edge_kernel(const float* __restrict__ noise,
                            const int* __restrict__ col,
                            const int* __restrict__ row,
                            float* __restrict__ out,
                            int E) {
    int lane = threadIdx.x & 31;
    int sub  = lane >> 3;
    int l8   = lane & 7;
    int warp  = blockIdx.x * (blockDim.x >> 5) + (threadIdx.x >> 5);
    int nwarp = gridDim.x * (blockDim.x >> 5);

    uint4 cu = *(const uint4*)&g_ch2[l8 * 4];
    uint4 wu = *(const uint4*)&g_w2h2[l8 * 4];
    const __half2* c2 = (const __half2*)&cu;
    const __half2* w2 = (const __half2*)&wu;
    float bias = g_c[HID];
    __half2 z2 = __float2half2_rn(0.f);

    for (int base = 8 * warp; base < E; base += 8 * nwarp) {
        int e0 = base + sub;
        int e1 = base + 4 + sub;
        bool ok0 = e0 < E, ok1 = e1 < E;
        int i0 = ok0 ? e0 : 0, i1 = ok1 ? e1 : 0;

        int ci0 = col[i0], ri0 = row[i0];
        int ci1 = col[i1], ri1 = row[i1];

        uint4 av0 = __ldg((const uint4*)(g_yh + (size_t)ci0 * 128 + l8 * 8));
        uint4 bv0 = __ldg((const uint4*)(g_yh + (size_t)ri0 * 128 + 64 + l8 * 8));
        uint4 av1 = __ldg((const uint4*)(g_yh + (size_t)ci1 * 128 + l8 * 8));
        uint4 bv1 = __ldg((const uint4*)(g_yh + (size_t)ri1 * 128 + 64 + l8 * 8));

        const __half2* ah0 = (const __half2*)&av0;
        const __half2* bh0 = (const __half2*)&bv0;
        const __half2* ah1 = (const __half2*)&av1;
        const __half2* bh1 = (const __half2*)&bv1;

        __half2 p0 = __hmax2(__hadd2(__hadd2(ah0[0], bh0[0]), c2[0]), z2);
        __half2 p1 = __hmax2(__hadd2(__hadd2(ah0[1], bh0[1]), c2[1]), z2);
        __half2 p2 = __hmax2(__hadd2(__hadd2(ah0[2], bh0[2]), c2[2]), z2);
        __half2 p3 = __hmax2(__hadd2(__hadd2(ah0[3], bh0[3]), c2[3]), z2);
        __half2 q0 = __hmax2(__hadd2(__hadd2(ah1[0], bh1[0]), c2[0]), z2);
        __half2 q1 = __hmax2(__hadd2(__hadd2(ah1[1], bh1[1]), c2[1]), z2);
        __half2 q2 = __hmax2(__hadd2(__hadd2(ah1[2], bh1[2]), c2[2]), z2);
        __half2 q3 = __hmax2(__hadd2(__hadd2(ah1[3], bh1[3]), c2[3]), z2);

        __half2 sa0 = __hfma2(p1, w2[1], __hmul2(p0, w2[0]));
        __half2 sb0 = __hfma2(p3, w2[3], __hmul2(p2, w2[2]));
        __half2 sa1 = __hfma2(q1, w2[1], __hmul2(q0, w2[0]));
        __half2 sb1 = __hfma2(q3, w2[3], __hmul2(q2, w2[2]));

        float2 fa0 = __half22float2(sa0), fb0 = __half22float2(sb0);
        float2 fa1 = __half22float2(sa1), fb1 = __half22float2(sb1);
        float s0 = (fa0.x + fa0.y) + (fb0.x + fb0.y);
        float s1 = (fa1.x + fa1.y) + (fb1.x + fb1.y);

        s0 += __shfl_xor_sync(0xffffffffu, s0, 4);
        s0 += __shfl_xor_sync(0xffffffffu, s0, 2);
        s0 += __shfl_xor_sync(0xffffffffu, s0, 1);
        s1 += __shfl_xor_sync(0xffffffffu, s1, 4);
        s1 += __shfl_xor_sync(0xffffffffu, s1, 2);
        s1 += __shfl_xor_sync(0xffffffffu, s1, 1);

        if (l8 == 0) {
            if (ok0) {
                float n = noise[e0];
                float t = n * __expf(s0 + bias);
                out[e0] = __fdividef(t, t + 1.f - n);
            }
            if (ok1) {
                float n = noise[e1];
                float t = n * __expf(s1 + bias);
                out[e1] = __fdividef(t, t + 1.f - n);
            }
        }
    }
}

// ---------------------------------------------------------------------------
extern "C" void kernel_launch(void* const* d_in, const int* in_sizes, int n_in,
                              void* d_out, int out_size) {
    const float* embed = (const float*)d_in[0];
    const float* W1    = (const float*)d_in[1];
    const float* b1    = (const float*)d_in[2];
    const float* W2    = (const float*)d_in[3];
    const float* b2    = (const float*)d_in[4];
    const float* noise = (const float*)d_in[5];
    const int*   col   = (const int*)d_in[6];
    const int*   row   = (const int*)d_in[7];
    const int*   srcp  = (const int*)d_in[8];
    const int*   dstp  = (const int*)d_in[9];

    int M = in_sizes[0] / D_FEAT;
    int E = in_sizes[6];

    cudaFuncSetAttribute(node_gemm_mma,
                         cudaFuncAttributeMaxDynamicSharedMemorySize, SM_TOTAL);

    int nblk = (M + 127) / 128;
    node_gemm_mma<<<nblk + 1, 512, SM_TOTAL>>>(embed, W1, b1, W2, b2,
                                               srcp, dstp, M, nblk);
    edge_kernel<<<4096, 256>>>(noise, col, row, (float*)d_out, E);
}

// round 13
// speedup vs baseline: 1.2699x; 1.2699x over previous
#include <cuda_runtime.h>
#include <cuda_fp16.h>
#include <math.h>
#include <stdint.h>

#define D_FEAT 128
#define HID 64
#define GRID_W 147          // persistent work CTAs; CTA GRID_W computes c

// Per-node projected features in fp16 (25.6 MB, L2-resident).
__device__ __half g_yh[(size_t)100000 * 128];
// c vector (float) + bias
__device__ float g_c[HID + 1];
// half2-packed c and W2 for the edge kernel
__device__ __half2 g_ch2[HID / 2];
__device__ __half2 g_w2h2[HID / 2];

// ---------------------------------------------------------------------------
// GEMM smem layout (bytes): B tile [128][132] f32 at 0, then two A stages
// [128][132] f32 each. Row stride 132 floats = 528 B -> bank(4g+tg) all
// distinct for the tf32 fragment pattern (conflict-free).
// ---------------------------------------------------------------------------
#define SROW32 132
#define SB_OFF 0
#define SB_BYTES (128 * SROW32 * 4)        // 67584
#define SA_OFF(buf) (SB_BYTES + (buf) * SB_BYTES)
#define SM_TOTAL (3 * SB_BYTES)            // 202752

__device__ __forceinline__ uint32_t smem_u32(const void* p) {
    uint32_t a;
    asm("{ .reg .u64 t; cvta.to.shared.u64 t, %1; cvt.u32.u64 %0, t; }"
        : "=r"(a) : "l"(p));
    return a;
}
__device__ __forceinline__ void cp16(uint32_t s, const void* g) {
    asm volatile("cp.async.cg.shared.global [%0], [%1], 16;" :: "r"(s), "l"(g));
}

__device__ __forceinline__ void mma_tf32(float* c, const uint32_t* a,
                                         const uint32_t* b) {
    asm volatile(
        "mma.sync.aligned.m16n8k8.row.col.f32.tf32.tf32.f32 "
        "{%0,%1,%2,%3}, {%4,%5,%6,%7}, {%8,%9}, {%0,%1,%2,%3};"
        : "+f"(c[0]), "+f"(c[1]), "+f"(c[2]), "+f"(c[3])
        : "r"(a[0]), "r"(a[1]), "r"(a[2]), "r"(a[3]), "r"(b[0]), "r"(b[1]));
}

// Issue async copy of tile 'row0' into stage buffer; zero-fill OOB rows.
__device__ __forceinline__ void load_tile_async(const float* __restrict__ embed,
                                                char* smem, uint32_t sbase,
                                                int stageOff, int row0, int M,
                                                int tid) {
    int rows = M - row0;
    if (rows > 128) rows = 128;
#pragma unroll
    for (int i = 0; i < 16; ++i) {
        int ch = tid + i * 256;
        int r = ch >> 5;
        int c = ch & 31;
        if (r < rows) {
            cp16(sbase + stageOff + r * 528 + c * 16,
                 embed + (size_t)(row0 + r) * 128 + c * 4);
        } else {
            *(float4*)(smem + stageOff + r * 528 + c * 16) =
                make_float4(0.f, 0.f, 0.f, 0.f);
        }
    }
}

// ---------------------------------------------------------------------------
// Kernel 1: persistent tf32 node GEMM + c-vector CTA.
// y[M x 128] = embed[M x 128] @ Wc[128 x 128], fp16 output to g_yh.
// 256 threads = 8 warps (4 M x 2 N), warp tile 32x64, K=128 via 16 k8-steps.
// ---------------------------------------------------------------------------
__global__ __launch_bounds__(256, 1)
void node_gemm_tf32(const float* __restrict__ embed,
                    const float* __restrict__ W1,
                    const float* __restrict__ b1,
                    const float* __restrict__ W2,
                    const float* __restrict__ b2,
                    const int* __restrict__ srcp,
                    const int* __restrict__ dstp,
                    int M, int ntiles) {
    extern __shared__ char smem[];
    int tid = threadIdx.x;

    if (blockIdx.x == GRID_W) {
        // ---- c vector CTA: c = emb[src]@W1[256:384] + emb[dst]@W1[384:512] + b1
        float* part = (float*)smem;   // [4][64]
        int j = tid & 63;
        int g = tid >> 6;   // 0..3
        int s = srcp[0];
        int d = dstp[0];
        const float* es = embed + (size_t)s * D_FEAT;
        const float* ed = embed + (size_t)d * D_FEAT;
        float acc = 0.f;
#pragma unroll 16
        for (int t = g * 64; t < g * 64 + 64; ++t) {
            float e = (t < 128) ? es[t] : ed[t - 128];
            acc = fmaf(e, W1[(256 + t) * HID + j], acc);  // 256+t == 384+(t-128)
        }
        part[g * 64 + j] = acc;
        __syncthreads();
        if (tid < 64) {
            float cj = b1[j] + part[j] + part[64 + j] + part[128 + j] + part[192 + j];
            g_c[j] = cj;
            part[j] = cj;
            if (j == 0) g_c[HID] = b2[0];
        }
        __syncthreads();
        if (tid < 32) {
            g_ch2[tid]  = __floats2half2_rn(part[2 * tid], part[2 * tid + 1]);
            g_w2h2[tid] = __floats2half2_rn(W2[2 * tid], W2[2 * tid + 1]);
        }
        return;
    }

    uint32_t sbase = smem_u32(smem);

    // Prologue: kick off async load of this CTA's first tile into stage 0.
    load_tile_async(embed, smem, sbase, SA_OFF(0), blockIdx.x * 128, M, tid);
    asm volatile("cp.async.commit_group;");

    // Build B tile (WcT as f32): B[j][k] = Wc[k][j]. Coalesced W1 read.
    {
        float* sB = (float*)(smem + SB_OFF);
        for (int idx = tid; idx < 16384; idx += 256) {
            int r = idx >> 6;   // W1 row 0..255
            int c = idx & 63;
            int k = (r < 128) ? r : r - 128;
            int j = (r < 128) ? c : c + 64;
            sB[j * SROW32 + k] = W1[idx];
        }
    }

    int w    = tid >> 5;
    int lane = tid & 31;
    int g    = lane >> 2;
    int tg   = lane & 3;
    int mw   = (w & 3) * 32;
    int nw   = (w >> 2) * 64;

    const float* sB = (const float*)(smem + SB_OFF);
    const float* pb = sB + (nw + g) * SROW32 + tg;

    int buf = 0;
    for (int t = blockIdx.x; t < ntiles; t += GRID_W) {
        int tn = t + GRID_W;
        if (tn < ntiles) {
            load_tile_async(embed, smem, sbase, SA_OFF(buf ^ 1), tn * 128, M, tid);
            asm volatile("cp.async.commit_group;");
            asm volatile("cp.async.wait_group 1;");
        } else {
            asm volatile("cp.async.wait_group 0;");
        }
        __syncthreads();   // stage[buf] fully resident

        const float* sA = (const float*)(smem + SA_OFF(buf));
        const float* pa = sA + (mw + g) * SROW32 + tg;

        float acc[2][8][4];
#pragma unroll
        for (int mi = 0; mi < 2; ++mi)
#pragma unroll
            for (int nj = 0; nj < 8; ++nj)
#pragma unroll
                for (int q = 0; q < 4; ++q) acc[mi][nj][q] = 0.f;

#pragma unroll
        for (int ks = 0; ks < 16; ++ks) {
            int k0 = ks * 8;
            uint32_t a[2][4];
#pragma unroll
            for (int mi = 0; mi < 2; ++mi) {
                const uint32_t* p = (const uint32_t*)(pa + mi * 16 * SROW32 + k0);
                a[mi][0] = p[0];
                a[mi][1] = p[8 * SROW32];
                a[mi][2] = p[4];
                a[mi][3] = p[8 * SROW32 + 4];
            }
            uint32_t b[8][2];
#pragma unroll
            for (int nj = 0; nj < 8; ++nj) {
                const uint32_t* p = (const uint32_t*)(pb + nj * 8 * SROW32 + k0);
                b[nj][0] = p[0];
                b[nj][1] = p[4];
            }
#pragma unroll
            for (int mi = 0; mi < 2; ++mi)
#pragma unroll
                for (int nj = 0; nj < 8; ++nj)
                    mma_tf32(acc[mi][nj], a[mi], b[nj]);
        }

        // Epilogue: fp16 half2 stores to g_yh
        int row0 = t * 128;
#pragma unroll
        for (int mi = 0; mi < 2; ++mi) {
            int r0 = row0 + mw + mi * 16 + g;
            int r1 = r0 + 8;
#pragma unroll
            for (int nj = 0; nj < 8; ++nj) {
                int jc = nw + nj * 8 + tg * 2;
                if (r0 < M)
                    *(__half2*)(g_yh + (size_t)r0 * 128 + jc) =
                        __floats2half2_rn(acc[mi][nj][0], acc[mi][nj][1]);
                if (r1 < M)
                    *(__half2*)(g_yh + (size_t)r1 * 128 + jc) =
                        __floats2half2_rn(acc[mi][nj][2], acc[mi][nj][3]);
            }
        }
        __syncthreads();   // done reading stage[buf] before it is refilled
        buf ^= 1;
    }
}

// ---------------------------------------------------------------------------
// Kernel 2: edge kernel — 8 edges per warp iteration (2 quads), 8 lanes/edge,
// half2 math. Gate: sigmoid(logit(n)+s) == n*exp(s) / (n*exp(s) + 1 - n).
// ---------------------------------------------------------------------------
__global__ void edge_kernel(const float* __restrict__ noise,
                            const int* __restrict__ col,
                            const int* __restrict__ row,
                            float* __restrict__ out,
                            int E) {
    int lane = threadIdx.x & 31;
    int sub  = lane >> 3;
    int l8   = lane & 7;
    int warp  = blockIdx.x * (blockDim.x >> 5) + (threadIdx.x >> 5);
    int nwarp = gridDim.x * (blockDim.x >> 5);

    uint4 cu = *(const uint4*)&g_ch2[l8 * 4];
    uint4 wu = *(const uint4*)&g_w2h2[l8 * 4];
    const __half2* c2 = (const __half2*)&cu;
    const __half2* w2 = (const __half2*)&wu;
    float bias = g_c[HID];
    __half2 z2 = __float2half2_rn(0.f);

    for (int base = 8 * warp; base < E; base += 8 * nwarp) {
        int e0 = base + sub;
        int e1 = base + 4 + sub;
        bool ok0 = e0 < E, ok1 = e1 < E;
        int i0 = ok0 ? e0 : 0, i1 = ok1 ? e1 : 0;

        int ci0 = col[i0], ri0 = row[i0];
        int ci1 = col[i1], ri1 = row[i1];

        uint4 av0 = __ldg((const uint4*)(g_yh + (size_t)ci0 * 128 + l8 * 8));
        uint4 bv0 = __ldg((const uint4*)(g_yh + (size_t)ri0 * 128 + 64 + l8 * 8));
        uint4 av1 = __ldg((const uint4*)(g_yh + (size_t)ci1 * 128 + l8 * 8));
        uint4 bv1 = __ldg((const uint4*)(g_yh + (size_t)ri1 * 128 + 64 + l8 * 8));

        const __half2* ah0 = (const __half2*)&av0;
        const __half2* bh0 = (const __half2*)&bv0;
        const __half2* ah1 = (const __half2*)&av1;
        const __half2* bh1 = (const __half2*)&bv1;

        __half2 p0 = __hmax2(__hadd2(__hadd2(ah0[0], bh0[0]), c2[0]), z2);
        __half2 p1 = __hmax2(__hadd2(__hadd2(ah0[1], bh0[1]), c2[1]), z2);
        __half2 p2 = __hmax2(__hadd2(__hadd2(ah0[2], bh0[2]), c2[2]), z2);
        __half2 p3 = __hmax2(__hadd2(__hadd2(ah0[3], bh0[3]), c2[3]), z2);
        __half2 q0 = __hmax2(__hadd2(__hadd2(ah1[0], bh1[0]), c2[0]), z2);
        __half2 q1 = __hmax2(__hadd2(__hadd2(ah1[1], bh1[1]), c2[1]), z2);
        __half2 q2 = __hmax2(__hadd2(__hadd2(ah1[2], bh1[2]), c2[2]), z2);
        __half2 q3 = __hmax2(__hadd2(__hadd2(ah1[3], bh1[3]), c2[3]), z2);

        __half2 sa0 = __hfma2(p1, w2[1], __hmul2(p0, w2[0]));
        __half2 sb0 = __hfma2(p3, w2[3], __hmul2(p2, w2[2]));
        __half2 sa1 = __hfma2(q1, w2[1], __hmul2(q0, w2[0]));
        __half2 sb1 = __hfma2(q3, w2[3], __hmul2(q2, w2[2]));

        float2 fa0 = __half22float2(sa0), fb0 = __half22float2(sb0);
        float2 fa1 = __half22float2(sa1), fb1 = __half22float2(sb1);
        float s0 = (fa0.x + fa0.y) + (fb0.x + fb0.y);
        float s1 = (fa1.x + fa1.y) + (fb1.x + fb1.y);

        s0 += __shfl_xor_sync(0xffffffffu, s0, 4);
        s0 += __shfl_xor_sync(0xffffffffu, s0, 2);
        s0 += __shfl_xor_sync(0xffffffffu, s0, 1);
        s1 += __shfl_xor_sync(0xffffffffu, s1, 4);
        s1 += __shfl_xor_sync(0xffffffffu, s1, 2);
        s1 += __shfl_xor_sync(0xffffffffu, s1, 1);

        if (l8 == 0) {
            if (ok0) {
                float n = noise[e0];
                float t = n * __expf(s0 + bias);
                out[e0] = __fdividef(t, t + 1.f - n);
            }
            if (ok1) {
                float n = noise[e1];
                float t = n * __expf(s1 + bias);
                out[e1] = __fdividef(t, t + 1.f - n);
            }
        }
    }
}

// ---------------------------------------------------------------------------
extern "C" void kernel_launch(void* const* d_in, const int* in_sizes, int n_in,
                              void* d_out, int out_size) {
    const float* embed = (const float*)d_in[0];
    const float* W1    = (const float*)d_in[1];
    const float* b1    = (const float*)d_in[2];
    const float* W2    = (const float*)d_in[3];
    const float* b2    = (const float*)d_in[4];
    const float* noise = (const float*)d_in[5];
    const int*   col   = (const int*)d_in[6];
    const int*   row   = (const int*)d_in[7];
    const int*   srcp  = (const int*)d_in[8];
    const int*   dstp  = (const int*)d_in[9];

    int M = in_sizes[0] / D_FEAT;
    int E = in_sizes[6];
    int ntiles = (M + 127) / 128;

    cudaFuncSetAttribute(node_gemm_tf32,
                         cudaFuncAttributeMaxDynamicSharedMemorySize, SM_TOTAL);

    node_gemm_tf32<<<GRID_W + 1, 256, SM_TOTAL>>>(embed, W1, b1, W2, b2,
                                                  srcp, dstp, M, ntiles);
    edge_kernel<<<4096, 256>>>(noise, col, row, (float*)d_out, E);
}

// round 15
// speedup vs baseline: 1.3857x; 1.0913x over previous
#include <cuda_runtime.h>
#include <cuda_fp16.h>
#include <math.h>
#include <stdint.h>

#define D_FEAT 128
#define HID 64
#define GRID_W 147          // persistent work CTAs; CTA GRID_W computes c

// Per-node projected features in fp16 (25.6 MB, L2-resident).
__device__ __half g_yh[(size_t)100000 * 128];
// c vector (float) + bias
__device__ float g_c[HID + 1];
// half2-packed c and W2 for the edge kernel
__device__ __half2 g_ch2[HID / 2];
__device__ __half2 g_w2h2[HID / 2];

// ---------------------------------------------------------------------------
// GEMM smem layout (bytes):
//   B fp16 [128][136h]  at 0        (34816)
//   A fp16 [128][136h]  at 34816    (34816)
//   stage f32 [128][132] at 69632   (67584)
// ---------------------------------------------------------------------------
#define SROW 272            // fp16 tile row stride in bytes (136 halves)
#define SROW32 132          // stage row stride in floats (528 B)
#define SM_BH 0
#define SM_AH 34816
#define SM_ST 69632
#define SM_TOTAL 137216

__device__ __forceinline__ uint32_t smem_u32(const void* p) {
    uint32_t a;
    asm("{ .reg .u64 t; cvta.to.shared.u64 t, %1; cvt.u32.u64 %0, t; }"
        : "=r"(a) : "l"(p));
    return a;
}
__device__ __forceinline__ void cp16(uint32_t s, const void* g) {
    asm volatile("cp.async.cg.shared.global [%0], [%1], 16;" :: "r"(s), "l"(g));
}

__device__ __forceinline__ void mma16816(float* c, const uint32_t* a,
                                         const uint32_t* b) {
    asm volatile(
        "mma.sync.aligned.m16n8k16.row.col.f32.f16.f16.f32 "
        "{%0,%1,%2,%3}, {%4,%5,%6,%7}, {%8,%9}, {%0,%1,%2,%3};"
        : "+f"(c[0]), "+f"(c[1]), "+f"(c[2]), "+f"(c[3])
        : "r"(a[0]), "r"(a[1]), "r"(a[2]), "r"(a[3]), "r"(b[0]), "r"(b[1]));
}

// Issue async copy of tile 'row0' into the f32 stage; zero-fill OOB rows.
__device__ __forceinline__ void load_tile_async(const float* __restrict__ embed,
                                                char* smem, uint32_t sbase,
                                                int row0, int M, int tid) {
    int rows = M - row0;
    if (rows > 128) rows = 128;
#pragma unroll
    for (int i = 0; i < 16; ++i) {
        int ch = tid + i * 256;
        int r = ch >> 5;
        int c = ch & 31;
        if (r < rows) {
            cp16(sbase + SM_ST + r * 528 + c * 16,
                 embed + (size_t)(row0 + r) * 128 + c * 4);
        } else {
            *(float4*)(smem + SM_ST + r * 528 + c * 16) =
                make_float4(0.f, 0.f, 0.f, 0.f);
        }
    }
}

// ---------------------------------------------------------------------------
// Kernel 1: persistent fp16 node GEMM (m16n8k16) + c-vector CTA.
// y[M x 128] = embed[M x 128] @ Wc[128 x 128], fp16 output to g_yh.
// 256 threads = 8 warps (4 M x 2 N), warp tile 32x64, K=128 via 8 k16-steps.
// ---------------------------------------------------------------------------
__global__ __launch_bounds__(256, 1)
void node_gemm_mma(const float* __restrict__ embed,
                   const float* __restrict__ W1,
                   const float* __restrict__ b1,
                   const float* __restrict__ W2,
                   const float* __restrict__ b2,
                   const int* __restrict__ srcp,
                   const int* __restrict__ dstp,
                   int M, int ntiles) {
    extern __shared__ char smem[];
    int tid = threadIdx.x;

    if (blockIdx.x == GRID_W) {
        // ---- c vector CTA
        float* part = (float*)smem;   // [4][64]
        int j = tid & 63;
        int g = tid >> 6;   // 0..3
        int s = srcp[0];
        int d = dstp[0];
        const float* es = embed + (size_t)s * D_FEAT;
        const float* ed = embed + (size_t)d * D_FEAT;
        float acc = 0.f;
#pragma unroll 16
        for (int t = g * 64; t < g * 64 + 64; ++t) {
            float e = (t < 128) ? es[t] : ed[t - 128];
            acc = fmaf(e, W1[(256 + t) * HID + j], acc);  // 256+t == 384+(t-128)
        }
        part[g * 64 + j] = acc;
        __syncthreads();
        if (tid < 64) {
            float cj = b1[j] + part[j] + part[64 + j] + part[128 + j] + part[192 + j];
            g_c[j] = cj;
            part[j] = cj;
            if (j == 0) g_c[HID] = b2[0];
        }
        __syncthreads();
        if (tid < 32) {
            g_ch2[tid]  = __floats2half2_rn(part[2 * tid], part[2 * tid + 1]);
            g_w2h2[tid] = __floats2half2_rn(W2[2 * tid], W2[2 * tid + 1]);
        }
        return;
    }

    uint32_t sbase = smem_u32(smem);

    // Prologue: async-load this CTA's first tile into the stage.
    load_tile_async(embed, smem, sbase, blockIdx.x * 128, M, tid);
    asm volatile("cp.async.commit_group;");

    // Build B tile once (WcT fp16): B[j][k] = Wc[k][j], half2 pairs along k.
    for (int idx = tid; idx < 8192; idx += 256) {
        int j  = idx & 127;
        int kh = idx >> 7;
        int c  = (j < 64) ? j : j - 64;
        int base = (j < 64) ? 0 : 128;
        float v0 = W1[(base + 2 * kh) * HID + c];
        float v1 = W1[(base + 2 * kh + 1) * HID + c];
        *(__half2*)(smem + SM_BH + j * SROW + 4 * kh) = __floats2half2_rn(v0, v1);
    }

    int w    = tid >> 5;
    int lane = tid & 31;
    int g    = lane >> 2;
    int tg   = lane & 3;
    int mw   = (w & 3) * 32;
    int nw   = (w >> 2) * 64;

    const char* pa0 = smem + SM_AH + (mw + g) * SROW + tg * 4;
    const char* pb0 = smem + SM_BH + (nw + g) * SROW + tg * 4;

    for (int t = blockIdx.x; t < ntiles; t += GRID_W) {
        asm volatile("cp.async.wait_group 0;");
        __syncthreads();   // stage resident; previous MMA reads of A done

        // Convert stage f32 -> A fp16 smem
        for (int idx = tid; idx < 2048; idx += 256) {
            int r  = idx >> 4;
            int cc = idx & 15;
            const float* sp = (const float*)(smem + SM_ST + r * 528 + cc * 32);
            float4 f0 = *(const float4*)sp;
            float4 f1 = *(const float4*)(sp + 4);
            __half2 h[4];
            h[0] = __floats2half2_rn(f0.x, f0.y);
            h[1] = __floats2half2_rn(f0.z, f0.w);
            h[2] = __floats2half2_rn(f1.x, f1.y);
            h[3] = __floats2half2_rn(f1.z, f1.w);
            *(uint4*)(smem + SM_AH + r * SROW + cc * 16) = *(uint4*)h;
        }
        __syncthreads();   // A ready; stage free

        int tn = t + GRID_W;
        if (tn < ntiles) {
            load_tile_async(embed, smem, sbase, tn * 128, M, tid);
            asm volatile("cp.async.commit_group;");
        }

        float acc[2][8][4];
#pragma unroll
        for (int mi = 0; mi < 2; ++mi)
#pragma unroll
            for (int nj = 0; nj < 8; ++nj)
#pragma unroll
                for (int q = 0; q < 4; ++q) acc[mi][nj][q] = 0.f;

#pragma unroll
        for (int ks = 0; ks < 8; ++ks) {
            int kb = ks * 32;
            uint32_t a[2][4];
#pragma unroll
            for (int mi = 0; mi < 2; ++mi) {
                const char* p = pa0 + mi * 16 * SROW + kb;
                a[mi][0] = *(const uint32_t*)p;
                a[mi][1] = *(const uint32_t*)(p + 8 * SROW);
                a[mi][2] = *(const uint32_t*)(p + 16);
                a[mi][3] = *(const uint32_t*)(p + 8 * SROW + 16);
            }
            uint32_t b[8][2];
#pragma unroll
            for (int nj = 0; nj < 8; ++nj) {
                const char* p = pb0 + nj * 8 * SROW + kb;
                b[nj][0] = *(const uint32_t*)p;
                b[nj][1] = *(const uint32_t*)(p + 16);
            }
#pragma unroll
            for (int mi = 0; mi < 2; ++mi)
#pragma unroll
                for (int nj = 0; nj < 8; ++nj)
                    mma16816(acc[mi][nj], a[mi], b[nj]);
        }

        // Epilogue: fp16 half2 stores to g_yh
        int row0 = t * 128;
#pragma unroll
        for (int mi = 0; mi < 2; ++mi) {
            int r0 = row0 + mw + mi * 16 + g;
            int r1 = r0 + 8;
#pragma unroll
            for (int nj = 0; nj < 8; ++nj) {
                int jc = nw + nj * 8 + tg * 2;
                if (r0 < M)
                    *(__half2*)(g_yh + (size_t)r0 * 128 + jc) =
                        __floats2half2_rn(acc[mi][nj][0], acc[mi][nj][1]);
                if (r1 < M)
                    *(__half2*)(g_yh + (size_t)r1 * 128 + jc) =
                        __floats2half2_rn(acc[mi][nj][2], acc[mi][nj][3]);
            }
        }
    }
}

// ---------------------------------------------------------------------------
// Kernel 2: edge kernel — 8 edges per warp iteration (2 quads), 8 lanes/edge,
// half2 math. launch_bounds(256,8) -> <=32 regs -> full occupancy.
// Gate: sigmoid(logit(n)+s) == n*exp(s) / (n*exp(s) + 1 - n).
// ---------------------------------------------------------------------------
__global__ __launch_bounds__(256, 8)
void edge_kernel(const float* __restrict__ noise,
                 const int* __restrict__ col,
                 const int* __restrict__ row,
                 float* __restrict__ out,
                 int E) {
    int lane = threadIdx.x & 31;
    int sub  = lane >> 3;
    int l8   = lane & 7;
    int warp  = blockIdx.x * (blockDim.x >> 5) + (threadIdx.x >> 5);
    int nwarp = gridDim.x * (blockDim.x >> 5);

    uint4 cu = *(const uint4*)&g_ch2[l8 * 4];
    uint4 wu = *(const uint4*)&g_w2h2[l8 * 4];
    const __half2* c2 = (const __half2*)&cu;
    const __half2* w2 = (const __half2*)&wu;
    float bias = g_c[HID];
    __half2 z2 = __float2half2_rn(0.f);

    for (int base = 8 * warp; base < E; base += 8 * nwarp) {
        int e0 = base + sub;
        int e1 = base + 4 + sub;
        bool ok0 = e0 < E, ok1 = e1 < E;
        int i0 = ok0 ? e0 : 0, i1 = ok1 ? e1 : 0;

        int ci0 = col[i0], ri0 = row[i0];
        int ci1 = col[i1], ri1 = row[i1];

        uint4 av0 = __ldg((const uint4*)(g_yh + (size_t)ci0 * 128 + l8 * 8));
        uint4 bv0 = __ldg((const uint4*)(g_yh + (size_t)ri0 * 128 + 64 + l8 * 8));
        uint4 av1 = __ldg((const uint4*)(g_yh + (size_t)ci1 * 128 + l8 * 8));
        uint4 bv1 = __ldg((const uint4*)(g_yh + (size_t)ri1 * 128 + 64 + l8 * 8));

        const __half2* ah0 = (const __half2*)&av0;
        const __half2* bh0 = (const __half2*)&bv0;
        const __half2* ah1 = (const __half2*)&av1;
        const __half2* bh1 = (const __half2*)&bv1;

        __half2 p0 = __hmax2(__hadd2(__hadd2(ah0[0], bh0[0]), c2[0]), z2);
        __half2 p1 = __hmax2(__hadd2(__hadd2(ah0[1], bh0[1]), c2[1]), z2);
        __half2 p2 = __hmax2(__hadd2(__hadd2(ah0[2], bh0[2]), c2[2]), z2);
        __half2 p3 = __hmax2(__hadd2(__hadd2(ah0[3], bh0[3]), c2[3]), z2);
        __half2 q0 = __hmax2(__hadd2(__hadd2(ah1[0], bh1[0]), c2[0]), z2);
        __half2 q1 = __hmax2(__hadd2(__hadd2(ah1[1], bh1[1]), c2[1]), z2);
        __half2 q2 = __hmax2(__hadd2(__hadd2(ah1[2], bh1[2]), c2[2]), z2);
        __half2 q3 = __hmax2(__hadd2(__hadd2(ah1[3], bh1[3]), c2[3]), z2);

        __half2 sa0 = __hfma2(p1, w2[1], __hmul2(p0, w2[0]));
        __half2 sb0 = __hfma2(p3, w2[3], __hmul2(p2, w2[2]));
        __half2 sa1 = __hfma2(q1, w2[1], __hmul2(q0, w2[0]));
        __half2 sb1 = __hfma2(q3, w2[3], __hmul2(q2, w2[2]));

        float2 fa0 = __half22float2(sa0), fb0 = __half22float2(sb0);
        float2 fa1 = __half22float2(sa1), fb1 = __half22float2(sb1);
        float s0 = (fa0.x + fa0.y) + (fb0.x + fb0.y);
        float s1 = (fa1.x + fa1.y) + (fb1.x + fb1.y);

        s0 += __shfl_xor_sync(0xffffffffu, s0, 4);
        s0 += __shfl_xor_sync(0xffffffffu, s0, 2);
        s0 += __shfl_xor_sync(0xffffffffu, s0, 1);
        s1 += __shfl_xor_sync(0xffffffffu, s1, 4);
        s1 += __shfl_xor_sync(0xffffffffu, s1, 2);
        s1 += __shfl_xor_sync(0xffffffffu, s1, 1);

        if (l8 == 0) {
            if (ok0) {
                float n = noise[e0];
                float t = n * __expf(s0 + bias);
                out[e0] = __fdividef(t, t + 1.f - n);
            }
            if (ok1) {
                float n = noise[e1];
                float t = n * __expf(s1 + bias);
                out[e1] = __fdividef(t, t + 1.f - n);
            }
        }
    }
}

// ---------------------------------------------------------------------------
extern "C" void kernel_launch(void* const* d_in, const int* in_sizes, int n_in,
                              void* d_out, int out_size) {
    const float* embed = (const float*)d_in[0];
    const float* W1    = (const float*)d_in[1];
    const float* b1    = (const float*)d_in[2];
    const float* W2    = (const float*)d_in[3];
    const float* b2    = (const float*)d_in[4];
    const float* noise = (const float*)d_in[5];
    const int*   col   = (const int*)d_in[6];
    const int*   row   = (const int*)d_in[7];
    const int*   srcp  = (const int*)d_in[8];
    const int*   dstp  = (const int*)d_in[9];

    int M = in_sizes[0] / D_FEAT;
    int E = in_sizes[6];
    int ntiles = (M + 127) / 128;

    cudaFuncSetAttribute(node_gemm_mma,
                         cudaFuncAttributeMaxDynamicSharedMemorySize, SM_TOTAL);

    node_gemm_mma<<<GRID_W + 1, 256, SM_TOTAL>>>(embed, W1, b1, W2, b2,
                                                 srcp, dstp, M, ntiles);
    edge_kernel<<<4096, 256>>>(noise, col, row, (float*)d_out, E);
}